// round 11
// baseline (speedup 1.0000x reference)
#include <cuda_runtime.h>
#include <cstdint>
#include <math.h>

#define BATCH 256
#define SEQ   512
#define FEAT  26
#define HID   512
#define MLPH  256
#define NCLS  20

// ---------------- scratch (device globals; no allocations) ----------------
__device__ float g_h0[BATCH * HID];                       // 0.5 MB
__device__ float g_c [BATCH * HID];                       // 0.5 MB
__device__ float g_hs[(size_t)BATCH * SEQ * HID];         // 256 MB
__device__ float g_hid[(size_t)BATCH * SEQ * MLPH];       // 128 MB

// ---------------- tf32 mma helpers ----------------
__device__ __forceinline__ uint32_t f2tf(float f) {
    uint32_t u;
    asm("cvt.rna.tf32.f32 %0, %1;" : "=r"(u) : "f"(f));
    return u;
}

__device__ __forceinline__ void mma_tf32(float c[4],
                                         uint32_t a0, uint32_t a1, uint32_t a2, uint32_t a3,
                                         uint32_t b0, uint32_t b1) {
    asm volatile(
        "mma.sync.aligned.m16n8k8.row.col.f32.tf32.tf32.f32 "
        "{%0,%1,%2,%3},{%4,%5,%6,%7},{%8,%9},{%0,%1,%2,%3};\n"
        : "+f"(c[0]), "+f"(c[1]), "+f"(c[2]), "+f"(c[3])
        : "r"(a0), "r"(a1), "r"(a2), "r"(a3), "r"(b0), "r"(b1));
}

constexpr int BK   = 32;   // K chunk
constexpr int KPAD = 36;   // padded smem K stride (conflict-free fragment loads)

// One 32-wide K chunk of MMAs. Block tile 64x64, 8 warps as 4(m) x 2(n),
// each warp m16 x n32 -> acc[4][4].
__device__ __forceinline__ void mma_chunk(float acc[4][4],
                                          const uint32_t (*As)[KPAD],
                                          const uint32_t (*Bs)[KPAD],
                                          int wm, int wn, int lane) {
    const int g  = lane >> 2;   // group id 0..7
    const int tg = lane & 3;    // thread in group 0..3
#pragma unroll
    for (int k8 = 0; k8 < 4; k8++) {
        const int kk = k8 * 8 + tg;
        const int ar = wm * 16 + g;
        uint32_t a0 = As[ar][kk];
        uint32_t a1 = As[ar + 8][kk];
        uint32_t a2 = As[ar][kk + 4];
        uint32_t a3 = As[ar + 8][kk + 4];
#pragma unroll
        for (int nn = 0; nn < 4; nn++) {
            const int br = wn * 32 + nn * 8 + g;
            mma_tf32(acc[nn], a0, a1, a2, a3, Bs[br][kk], Bs[br][kk + 4]);
        }
    }
}

// ---------------- init ----------------
__global__ void init_kernel() {
    int i = blockIdx.x * blockDim.x + threadIdx.x;
    if (i < BATCH * HID) {
        g_h0[i] = 0.0f;
        g_c[i]  = 0.0f;
    }
}

// ---------------- LSTM step ----------------
// grid = (4 batch-tiles, 32 unit-tiles), 256 threads.
// Block computes z[64 batch x (4 gates x 16 units)], then gate update in-kernel.
__global__ void __launch_bounds__(256, 1)
lstm_step_kernel(const float* __restrict__ x,
                 const float* __restrict__ w_ih,
                 const float* __restrict__ w_hh,
                 const float* __restrict__ b_ih,
                 const float* __restrict__ b_hh,
                 int t) {
    __shared__ uint32_t As[64][KPAD];
    __shared__ uint32_t Bs[64][KPAD];
    __shared__ float    zs[64][68];

    const int tid  = threadIdx.x;
    const int lane = tid & 31;
    const int warp = tid >> 5;
    const int wm   = warp >> 1;   // 0..3
    const int wn   = warp & 1;    // 0..1
    const int m0   = blockIdx.x * 64;
    const int u0   = blockIdx.y * 16;

    const float* hprev;
    long hstride;
    if (t == 0) { hprev = g_h0;                       hstride = HID; }
    else        { hprev = g_hs + (long)(t - 1) * HID; hstride = (long)SEQ * HID; }

    float acc[4][4];
#pragma unroll
    for (int i = 0; i < 4; i++)
#pragma unroll
        for (int j = 0; j < 4; j++) acc[i][j] = 0.0f;

    // per-thread global-load coordinates: 2 float4 per matrix per chunk
    const int r0 = tid >> 3;          // rows 0..31 (second set +32)
    const int c0 = (tid & 7) * 4;     // col group within 32

    float4 aR[2], bR[2];

    // ---- preload chunk 0 (h) ----
#pragma unroll
    for (int i = 0; i < 2; i++) {
        int row = r0 + i * 32;
        aR[i] = *(const float4*)(hprev + (long)(m0 + row) * hstride + c0);
        int ng = (row >> 4) * HID + u0 + (row & 15);   // gate*H + unit
        bR[i] = *(const float4*)(w_hh + (long)ng * HID + c0);
    }
#pragma unroll
    for (int i = 0; i < 2; i++) {
        int row = r0 + i * 32;
        As[row][c0 + 0] = f2tf(aR[i].x); As[row][c0 + 1] = f2tf(aR[i].y);
        As[row][c0 + 2] = f2tf(aR[i].z); As[row][c0 + 3] = f2tf(aR[i].w);
        Bs[row][c0 + 0] = f2tf(bR[i].x); Bs[row][c0 + 1] = f2tf(bR[i].y);
        Bs[row][c0 + 2] = f2tf(bR[i].z); Bs[row][c0 + 3] = f2tf(bR[i].w);
    }
    __syncthreads();

    const int NCHUNK = HID / BK;  // 16 h-chunks, then 1 x-chunk => 17 total
    for (int kc = 0; kc < NCHUNK + 1; kc++) {
        // prefetch next chunk into registers while MMAs run on smem
        if (kc + 1 < NCHUNK) {
#pragma unroll
            for (int i = 0; i < 2; i++) {
                int row = r0 + i * 32;
                aR[i] = *(const float4*)(hprev + (long)(m0 + row) * hstride + (kc + 1) * BK + c0);
                int ng = (row >> 4) * HID + u0 + (row & 15);
                bR[i] = *(const float4*)(w_hh + (long)ng * HID + (kc + 1) * BK + c0);
            }
        } else if (kc + 1 == NCHUNK) {
            // x / w_ih chunk (K = 26, zero-padded to 32)
#pragma unroll
            for (int i = 0; i < 2; i++) {
                int row = r0 + i * 32;
                const float* xa = x + (long)(m0 + row) * SEQ * FEAT + (long)t * FEAT;
                int ng = (row >> 4) * HID + u0 + (row & 15);
                const float* wb = w_ih + (long)ng * FEAT;
                float4 a, b;
                a.x = (c0 + 0 < FEAT) ? xa[c0 + 0] : 0.0f;
                a.y = (c0 + 1 < FEAT) ? xa[c0 + 1] : 0.0f;
                a.z = (c0 + 2 < FEAT) ? xa[c0 + 2] : 0.0f;
                a.w = (c0 + 3 < FEAT) ? xa[c0 + 3] : 0.0f;
                b.x = (c0 + 0 < FEAT) ? wb[c0 + 0] : 0.0f;
                b.y = (c0 + 1 < FEAT) ? wb[c0 + 1] : 0.0f;
                b.z = (c0 + 2 < FEAT) ? wb[c0 + 2] : 0.0f;
                b.w = (c0 + 3 < FEAT) ? wb[c0 + 3] : 0.0f;
                aR[i] = a; bR[i] = b;
            }
        }

        mma_chunk(acc, As, Bs, wm, wn, lane);

        if (kc + 1 < NCHUNK + 1) {
            __syncthreads();
#pragma unroll
            for (int i = 0; i < 2; i++) {
                int row = r0 + i * 32;
                As[row][c0 + 0] = f2tf(aR[i].x); As[row][c0 + 1] = f2tf(aR[i].y);
                As[row][c0 + 2] = f2tf(aR[i].z); As[row][c0 + 3] = f2tf(aR[i].w);
                Bs[row][c0 + 0] = f2tf(bR[i].x); Bs[row][c0 + 1] = f2tf(bR[i].y);
                Bs[row][c0 + 2] = f2tf(bR[i].z); Bs[row][c0 + 3] = f2tf(bR[i].w);
            }
            __syncthreads();
        }
    }

    // ---- stage z tile to smem ----
    __syncthreads();
    {
        const int row = wm * 16 + (lane >> 2);
        const int cq  = 2 * (lane & 3);
#pragma unroll
        for (int nn = 0; nn < 4; nn++) {
            const int col = wn * 32 + nn * 8 + cq;
            zs[row][col]     = acc[nn][0];
            zs[row][col + 1] = acc[nn][1];
            zs[row + 8][col]     = acc[nn][2];
            zs[row + 8][col + 1] = acc[nn][3];
        }
    }
    __syncthreads();

    // ---- gate update: 64 batch x 16 units ----
    for (int it = tid; it < 64 * 16; it += 256) {
        const int bl = it >> 4;
        const int jj = it & 15;
        const int b  = m0 + bl;
        const int j  = u0 + jj;

        float zi = zs[bl][jj]      + b_ih[j]           + b_hh[j];
        float zf = zs[bl][16 + jj] + b_ih[HID + j]     + b_hh[HID + j];
        float zg = zs[bl][32 + jj] + b_ih[2 * HID + j] + b_hh[2 * HID + j];
        float zo = zs[bl][48 + jj] + b_ih[3 * HID + j] + b_hh[3 * HID + j];

        float is = 1.0f / (1.0f + expf(-zi));
        float fs = 1.0f / (1.0f + expf(-zf));
        float gt = tanhf(zg);
        float os = 1.0f / (1.0f + expf(-zo));

        float cold = g_c[b * HID + j];
        float cn   = fs * cold + is * gt;
        g_c[b * HID + j] = cn;
        g_hs[(long)b * SEQ * HID + (long)t * HID + j] = os * tanhf(cn);
    }
}

// ---------------- MLP layer 1: hid = relu(hs @ w1^T + b1) ----------------
// grid = (131072/64 row tiles, 256/64 col tiles), 256 threads.
__global__ void __launch_bounds__(256, 1)
mlp1_kernel(const float* __restrict__ w1, const float* __restrict__ b1) {
    __shared__ uint32_t As[64][KPAD];
    __shared__ uint32_t Bs[64][KPAD];

    const int tid  = threadIdx.x;
    const int lane = tid & 31;
    const int warp = tid >> 5;
    const int wm   = warp >> 1;
    const int wn   = warp & 1;
    const long row0 = (long)blockIdx.x * 64;
    const int  n0   = blockIdx.y * 64;

    float acc[4][4];
#pragma unroll
    for (int i = 0; i < 4; i++)
#pragma unroll
        for (int j = 0; j < 4; j++) acc[i][j] = 0.0f;

    const int r0 = tid >> 3;
    const int c0 = (tid & 7) * 4;
    float4 aR[2], bR[2];

#pragma unroll
    for (int i = 0; i < 2; i++) {
        int row = r0 + i * 32;
        aR[i] = *(const float4*)(g_hs + (row0 + row) * HID + c0);
        bR[i] = *(const float4*)(w1 + (long)(n0 + row) * HID + c0);
    }
#pragma unroll
    for (int i = 0; i < 2; i++) {
        int row = r0 + i * 32;
        As[row][c0 + 0] = f2tf(aR[i].x); As[row][c0 + 1] = f2tf(aR[i].y);
        As[row][c0 + 2] = f2tf(aR[i].z); As[row][c0 + 3] = f2tf(aR[i].w);
        Bs[row][c0 + 0] = f2tf(bR[i].x); Bs[row][c0 + 1] = f2tf(bR[i].y);
        Bs[row][c0 + 2] = f2tf(bR[i].z); Bs[row][c0 + 3] = f2tf(bR[i].w);
    }
    __syncthreads();

    const int NCHUNK = HID / BK;  // 16
    for (int kc = 0; kc < NCHUNK; kc++) {
        if (kc + 1 < NCHUNK) {
#pragma unroll
            for (int i = 0; i < 2; i++) {
                int row = r0 + i * 32;
                aR[i] = *(const float4*)(g_hs + (row0 + row) * HID + (kc + 1) * BK + c0);
                bR[i] = *(const float4*)(w1 + (long)(n0 + row) * HID + (kc + 1) * BK + c0);
            }
        }
        mma_chunk(acc, As, Bs, wm, wn, lane);
        if (kc + 1 < NCHUNK) {
            __syncthreads();
#pragma unroll
            for (int i = 0; i < 2; i++) {
                int row = r0 + i * 32;
                As[row][c0 + 0] = f2tf(aR[i].x); As[row][c0 + 1] = f2tf(aR[i].y);
                As[row][c0 + 2] = f2tf(aR[i].z); As[row][c0 + 3] = f2tf(aR[i].w);
                Bs[row][c0 + 0] = f2tf(bR[i].x); Bs[row][c0 + 1] = f2tf(bR[i].y);
                Bs[row][c0 + 2] = f2tf(bR[i].z); Bs[row][c0 + 3] = f2tf(bR[i].w);
            }
            __syncthreads();
        }
    }

    // epilogue: +b1, relu, store
    {
        const int cq = 2 * (lane & 3);
        const long rr = row0 + wm * 16 + (lane >> 2);
#pragma unroll
        for (int nn = 0; nn < 4; nn++) {
            const int col = n0 + wn * 32 + nn * 8 + cq;
            float bb0 = b1[col], bb1 = b1[col + 1];
            float2 v0 = make_float2(fmaxf(acc[nn][0] + bb0, 0.0f),
                                    fmaxf(acc[nn][1] + bb1, 0.0f));
            float2 v1 = make_float2(fmaxf(acc[nn][2] + bb0, 0.0f),
                                    fmaxf(acc[nn][3] + bb1, 0.0f));
            *(float2*)(g_hid + rr * MLPH + col)       = v0;
            *(float2*)(g_hid + (rr + 8) * MLPH + col) = v1;
        }
    }
}

// ---------------- MLP layer 2 + log_softmax ----------------
// 8 rows per block (one per warp); lanes 0..19 compute the 20 logits.
__global__ void __launch_bounds__(256, 2)
mlp2_kernel(const float* __restrict__ w2, const float* __restrict__ b2,
            float* __restrict__ out) {
    __shared__ float w2s[NCLS][MLPH + 1];  // stride 257 -> conflict-free
    __shared__ float hr[8][MLPH];

    const int tid  = threadIdx.x;
    const int lane = tid & 31;
    const int warp = tid >> 5;

    for (int e = tid; e < NCLS * MLPH; e += 256)
        w2s[e / MLPH][e % MLPH] = w2[e];

    const long row = (long)blockIdx.x * 8 + warp;
    for (int k = lane; k < MLPH; k += 32)
        hr[warp][k] = g_hid[row * MLPH + k];
    __syncthreads();

    float logit = -1e30f;
    if (lane < NCLS) {
        float s = b2[lane];
#pragma unroll 8
        for (int k = 0; k < MLPH; k++)
            s += hr[warp][k] * w2s[lane][k];
        logit = s;
    }
    float m = logit;
#pragma unroll
    for (int o = 16; o; o >>= 1) m = fmaxf(m, __shfl_xor_sync(0xffffffffu, m, o));
    float e = (lane < NCLS) ? expf(logit - m) : 0.0f;
    float ssum = e;
#pragma unroll
    for (int o = 16; o; o >>= 1) ssum += __shfl_xor_sync(0xffffffffu, ssum, o);
    if (lane < NCLS)
        out[row * NCLS + lane] = logit - m - logf(ssum);
}

// ---------------- launch ----------------
extern "C" void kernel_launch(void* const* d_in, const int* in_sizes, int n_in,
                              void* d_out, int out_size) {
    const float* x    = (const float*)d_in[0];
    const float* w_ih = (const float*)d_in[1];
    const float* w_hh = (const float*)d_in[2];
    const float* b_ih = (const float*)d_in[3];
    const float* b_hh = (const float*)d_in[4];
    const float* w1   = (const float*)d_in[5];
    const float* b1   = (const float*)d_in[6];
    const float* w2   = (const float*)d_in[7];
    const float* b2   = (const float*)d_in[8];
    float* out = (float*)d_out;

    init_kernel<<<(BATCH * HID + 255) / 256, 256>>>();

    dim3 sg(BATCH / 64, HID / 16);  // (4, 32)
    for (int t = 0; t < SEQ; t++)
        lstm_step_kernel<<<sg, 256>>>(x, w_ih, w_hh, b_ih, b_hh, t);

    mlp1_kernel<<<dim3((BATCH * SEQ) / 64, MLPH / 64), 256>>>(w1, b1);
    mlp2_kernel<<<(BATCH * SEQ) / 8, 256>>>(w2, b2, out);
}

// round 12
// speedup vs baseline: 1.2268x; 1.2268x over previous
#include <cuda_runtime.h>
#include <cuda_fp16.h>
#include <cstdint>
#include <math.h>

#define BATCH 256
#define SEQ   512
#define FEAT  26
#define HID   512
#define MLPH  256
#define NCLS  20
#define NBLK  128

// ---------------- device scratch (no allocations) ----------------
__device__ __half  g_hs[(size_t)BATCH * SEQ * HID];      // 128 MB, fp16 hidden states
__device__ float   g_hid[(size_t)BATCH * SEQ * MLPH];    // 128 MB
__device__ __half  g_whh_h[4 * HID * HID];               // 2 MB   w_hh fp16
__device__ __half  g_wih_h[4 * HID * 32];                // 128 KB w_ih fp16, K padded 26->32
__device__ __half  g_w1_h[MLPH * HID];                   // 256 KB w1 fp16
__device__ __half  g_x_h[(size_t)BATCH * SEQ * 32];      // 8 MB   x fp16, F padded 26->32
__device__ float   g_bias[4 * HID];                      // b_ih + b_hh
__device__ unsigned g_cnt;                               // grid barrier counter

// ---------------- fp16 mma (m16n8k16, fp32 accum) ----------------
__device__ __forceinline__ void mma_f16(float c[4],
                                        uint32_t a0, uint32_t a1, uint32_t a2, uint32_t a3,
                                        uint32_t b0, uint32_t b1) {
    asm volatile(
        "mma.sync.aligned.m16n8k16.row.col.f32.f16.f16.f32 "
        "{%0,%1,%2,%3},{%4,%5,%6,%7},{%8,%9},{%0,%1,%2,%3};\n"
        : "+f"(c[0]), "+f"(c[1]), "+f"(c[2]), "+f"(c[3])
        : "r"(a0), "r"(a1), "r"(a2), "r"(a3), "r"(b0), "r"(b1));
}

// smem tile: 64 rows x 32 halves (= 16 half2 words), padded to 20 words/row
// (word addr = row*20 + col: conflict-free for the fragment pattern g*20+tg)
#define KP2 20

__device__ __forceinline__ unsigned ld_acquire(const unsigned* p) {
    unsigned v;
    asm volatile("ld.acquire.gpu.u32 %0, [%1];" : "=r"(v) : "l"(p) : "memory");
    return v;
}

// one 32-half K chunk of MMAs: block tile 64x64, 8 warps = 4(m) x 2(n),
// warp m16 x n32, 2 k16-steps per chunk
__device__ __forceinline__ void mma_chunk(float acc[4][4],
                                          const uint32_t (*A)[KP2],
                                          const uint32_t (*B)[KP2],
                                          int wm, int wn, int lane) {
    const int g  = lane >> 2;
    const int tg = lane & 3;
#pragma unroll
    for (int s = 0; s < 2; s++) {
        const int kk = s * 8 + tg;
        const int ar = wm * 16 + g;
        uint32_t a0 = A[ar][kk];
        uint32_t a1 = A[ar + 8][kk];
        uint32_t a2 = A[ar][kk + 4];
        uint32_t a3 = A[ar + 8][kk + 4];
#pragma unroll
        for (int nn = 0; nn < 4; nn++) {
            const int br = wn * 32 + nn * 8 + g;
            mma_f16(acc[nn], a0, a1, a2, a3, B[br][kk], B[br][kk + 4]);
        }
    }
}

// ---------------- pre-pass: convert weights / bias / reset barrier ----------------
__global__ void prep_kernel(const float* __restrict__ w_ih, const float* __restrict__ w_hh,
                            const float* __restrict__ b_ih, const float* __restrict__ b_hh,
                            const float* __restrict__ w1) {
    long i = (long)blockIdx.x * blockDim.x + threadIdx.x;   // up to 2048*512
    if (i < (long)4 * HID * HID) g_whh_h[i] = __float2half_rn(w_hh[i]);
    if (i < (long)MLPH * HID)    g_w1_h[i]  = __float2half_rn(w1[i]);
    if (i < (long)4 * HID * 32) {
        int r = (int)(i >> 5), c = (int)(i & 31);
        g_wih_h[i] = __float2half_rn(c < FEAT ? w_ih[r * FEAT + c] : 0.0f);
    }
    if (i < 4 * HID) g_bias[i] = b_ih[i] + b_hh[i];
    if (i == 0) g_cnt = 0u;
}

__global__ void prepx_kernel(const float* __restrict__ x) {
    long i = (long)blockIdx.x * blockDim.x + threadIdx.x;   // BATCH*SEQ*32
    if (i < (long)BATCH * SEQ * 32) {
        long bs = i >> 5;
        int  c  = (int)(i & 31);
        g_x_h[i] = __float2half_rn(c < FEAT ? x[bs * FEAT + c] : 0.0f);
    }
}

// ---------------- load one K chunk (global -> regs) ----------------
__device__ __forceinline__ void load_chunk(int kc, int t, int m0, int r0, int sg, int ng,
                                           int4& aR, int4& bR) {
    if (kc < 16) {  // h @ w_hh
        aR = *reinterpret_cast<const int4*>(
                 g_hs + ((long)(m0 + r0) * SEQ + (t - 1)) * HID + kc * 32 + sg * 8);
        bR = *reinterpret_cast<const int4*>(
                 g_whh_h + (long)ng * HID + kc * 32 + sg * 8);
    } else {        // x @ w_ih  (padded K=32)
        aR = *reinterpret_cast<const int4*>(
                 g_x_h + ((long)(m0 + r0) * SEQ + t) * 32 + sg * 8);
        bR = *reinterpret_cast<const int4*>(g_wih_h + ng * 32 + sg * 8);
    }
}

// ---------------- persistent LSTM ----------------
// 128 blocks (4 batch-tiles x 32 unit-tiles), all co-resident; grid barrier per step.
__global__ void __launch_bounds__(256, 1) lstm_persist_kernel() {
    __shared__ uint32_t pool[2][2][64][KP2];   // [A/B][buf][row][word] = 20 KB
    __shared__ float    bsm[64];
    uint32_t (*As)[64][KP2] = pool[0];
    uint32_t (*Bs)[64][KP2] = pool[1];
    float (*zs)[68] = reinterpret_cast<float(*)[68]>(&pool[0][0][0][0]);  // 17.4KB alias

    const int tid  = threadIdx.x;
    const int lane = tid & 31;
    const int warp = tid >> 5;
    const int wm   = warp >> 1;
    const int wn   = warp & 1;
    const int blk  = blockIdx.x;
    const int m0   = (blk & 3) * 64;
    const int u0   = (blk >> 2) * 16;

    const int r0 = tid >> 2;       // load row 0..63
    const int sg = tid & 3;        // 8-half segment
    const int ng = (r0 >> 4) * HID + u0 + (r0 & 15);  // weight row: gate*H + unit

    if (tid < 64) bsm[tid] = g_bias[(tid >> 4) * HID + u0 + (tid & 15)];

    // cell state lives in registers: thread owns (batch bl, units jj0..jj0+3)
    const int bl  = tid >> 2;
    const int jj0 = (tid & 3) * 4;
    float creg[4] = {0.f, 0.f, 0.f, 0.f};

    unsigned target = 0;

    for (int t = 0; t < SEQ; t++) {
        float acc[4][4];
#pragma unroll
        for (int i = 0; i < 4; i++)
#pragma unroll
            for (int j = 0; j < 4; j++) acc[i][j] = 0.0f;

        const int nch = (t == 0) ? 1 : 17;   // t=0: h==0, only x chunk
        int4 aR, bR;
        load_chunk((t == 0) ? 16 : 0, t, m0, r0, sg, ng, aR, bR);
        *reinterpret_cast<int4*>(&As[0][r0][sg * 4]) = aR;
        *reinterpret_cast<int4*>(&Bs[0][r0][sg * 4]) = bR;
        __syncthreads();

        for (int ci = 0; ci < nch; ci++) {
            if (ci + 1 < nch) load_chunk(ci + 1, t, m0, r0, sg, ng, aR, bR);
            mma_chunk(acc, As[ci & 1], Bs[ci & 1], wm, wn, lane);
            if (ci + 1 < nch) {
                const int nb = (ci + 1) & 1;
                *reinterpret_cast<int4*>(&As[nb][r0][sg * 4]) = aR;
                *reinterpret_cast<int4*>(&Bs[nb][r0][sg * 4]) = bR;
                __syncthreads();
            }
        }
        __syncthreads();  // all MMA smem reads done before zs aliases the pool

        // stage z tile
        {
            const int row = wm * 16 + (lane >> 2);
            const int cq  = 2 * (lane & 3);
#pragma unroll
            for (int nn = 0; nn < 4; nn++) {
                const int col = wn * 32 + nn * 8 + cq;
                zs[row][col]         = acc[nn][0];
                zs[row][col + 1]     = acc[nn][1];
                zs[row + 8][col]     = acc[nn][2];
                zs[row + 8][col + 1] = acc[nn][3];
            }
        }
        __syncthreads();

        // gate update (c in registers), store h as fp16
        {
            float ho[4];
#pragma unroll
            for (int i = 0; i < 4; i++) {
                const int jj = jj0 + i;
                float zi = zs[bl][jj]      + bsm[jj];
                float zf = zs[bl][16 + jj] + bsm[16 + jj];
                float zg = zs[bl][32 + jj] + bsm[32 + jj];
                float zo = zs[bl][48 + jj] + bsm[48 + jj];
                float is = 1.0f / (1.0f + __expf(-zi));
                float fs = 1.0f / (1.0f + __expf(-zf));
                float gt = tanhf(zg);
                float os = 1.0f / (1.0f + __expf(-zo));
                float cn = fs * creg[i] + is * gt;
                creg[i]  = cn;
                ho[i]    = os * tanhf(cn);
            }
            __half2 p0 = __floats2half2_rn(ho[0], ho[1]);
            __half2 p1 = __floats2half2_rn(ho[2], ho[3]);
            uint2 v;
            v.x = *reinterpret_cast<uint32_t*>(&p0);
            v.y = *reinterpret_cast<uint32_t*>(&p1);
            *reinterpret_cast<uint2*>(
                g_hs + ((long)(m0 + bl) * SEQ + t) * HID + u0 + jj0) = v;
        }

        // grid barrier (monotonic counter; all 128 blocks resident)
        __threadfence();
        __syncthreads();
        if (tid == 0) {
            atomicAdd(&g_cnt, 1u);
            target += NBLK;
            while (ld_acquire(&g_cnt) < target) {}
        }
        __syncthreads();
    }
}

// ---------------- MLP layer 1 (fp16 mma): hid = relu(hs @ w1^T + b1) ----------------
__global__ void __launch_bounds__(256, 1) mlp1_kernel(const float* __restrict__ b1) {
    __shared__ uint32_t As[2][64][KP2];
    __shared__ uint32_t Bs[2][64][KP2];

    const int tid  = threadIdx.x;
    const int lane = tid & 31;
    const int warp = tid >> 5;
    const int wm   = warp >> 1;
    const int wn   = warp & 1;
    const long row0 = (long)blockIdx.x * 64;
    const int  n0   = blockIdx.y * 64;

    const int r0 = tid >> 2;
    const int sg = tid & 3;

    float acc[4][4];
#pragma unroll
    for (int i = 0; i < 4; i++)
#pragma unroll
        for (int j = 0; j < 4; j++) acc[i][j] = 0.0f;

    int4 aR, bR;
    aR = *reinterpret_cast<const int4*>(g_hs + (row0 + r0) * HID + sg * 8);
    bR = *reinterpret_cast<const int4*>(g_w1_h + (long)(n0 + r0) * HID + sg * 8);
    *reinterpret_cast<int4*>(&As[0][r0][sg * 4]) = aR;
    *reinterpret_cast<int4*>(&Bs[0][r0][sg * 4]) = bR;
    __syncthreads();

    const int NCH = HID / 32;  // 16
    for (int kc = 0; kc < NCH; kc++) {
        if (kc + 1 < NCH) {
            aR = *reinterpret_cast<const int4*>(
                     g_hs + (row0 + r0) * HID + (kc + 1) * 32 + sg * 8);
            bR = *reinterpret_cast<const int4*>(
                     g_w1_h + (long)(n0 + r0) * HID + (kc + 1) * 32 + sg * 8);
        }
        mma_chunk(acc, As[kc & 1], Bs[kc & 1], wm, wn, lane);
        if (kc + 1 < NCH) {
            const int nb = (kc + 1) & 1;
            *reinterpret_cast<int4*>(&As[nb][r0][sg * 4]) = aR;
            *reinterpret_cast<int4*>(&Bs[nb][r0][sg * 4]) = bR;
            __syncthreads();
        }
    }

    // epilogue: +b1, relu, store fp32
    {
        const int cq = 2 * (lane & 3);
        const long rr = row0 + wm * 16 + (lane >> 2);
#pragma unroll
        for (int nn = 0; nn < 4; nn++) {
            const int col = n0 + wn * 32 + nn * 8 + cq;
            float bb0 = b1[col], bb1 = b1[col + 1];
            float2 v0 = make_float2(fmaxf(acc[nn][0] + bb0, 0.0f),
                                    fmaxf(acc[nn][1] + bb1, 0.0f));
            float2 v1 = make_float2(fmaxf(acc[nn][2] + bb0, 0.0f),
                                    fmaxf(acc[nn][3] + bb1, 0.0f));
            *reinterpret_cast<float2*>(g_hid + rr * MLPH + col)       = v0;
            *reinterpret_cast<float2*>(g_hid + (rr + 8) * MLPH + col) = v1;
        }
    }
}

// ---------------- MLP layer 2 + log_softmax ----------------
__global__ void __launch_bounds__(256, 2)
mlp2_kernel(const float* __restrict__ w2, const float* __restrict__ b2,
            float* __restrict__ out) {
    __shared__ float w2s[NCLS][MLPH + 1];
    __shared__ float hr[8][MLPH];

    const int tid  = threadIdx.x;
    const int lane = tid & 31;
    const int warp = tid >> 5;

    for (int e = tid; e < NCLS * MLPH; e += 256)
        w2s[e / MLPH][e % MLPH] = w2[e];

    const long row = (long)blockIdx.x * 8 + warp;
    for (int k = lane; k < MLPH; k += 32)
        hr[warp][k] = g_hid[row * MLPH + k];
    __syncthreads();

    float logit = -1e30f;
    if (lane < NCLS) {
        float s = b2[lane];
#pragma unroll 8
        for (int k = 0; k < MLPH; k++)
            s += hr[warp][k] * w2s[lane][k];
        logit = s;
    }
    float m = logit;
#pragma unroll
    for (int o = 16; o; o >>= 1) m = fmaxf(m, __shfl_xor_sync(0xffffffffu, m, o));
    float e = (lane < NCLS) ? expf(logit - m) : 0.0f;
    float ssum = e;
#pragma unroll
    for (int o = 16; o; o >>= 1) ssum += __shfl_xor_sync(0xffffffffu, ssum, o);
    if (lane < NCLS)
        out[row * NCLS + lane] = logit - m - logf(ssum);
}

// ---------------- launch ----------------
extern "C" void kernel_launch(void* const* d_in, const int* in_sizes, int n_in,
                              void* d_out, int out_size) {
    const float* x    = (const float*)d_in[0];
    const float* w_ih = (const float*)d_in[1];
    const float* w_hh = (const float*)d_in[2];
    const float* b_ih = (const float*)d_in[3];
    const float* b_hh = (const float*)d_in[4];
    const float* w1   = (const float*)d_in[5];
    const float* b1   = (const float*)d_in[6];
    const float* w2   = (const float*)d_in[7];
    const float* b2   = (const float*)d_in[8];
    float* out = (float*)d_out;

    prep_kernel<<<(4 * HID * HID + 255) / 256, 256>>>(w_ih, w_hh, b_ih, b_hh, w1);
    prepx_kernel<<<((long)BATCH * SEQ * 32 + 255) / 256, 256>>>(x);

    lstm_persist_kernel<<<NBLK, 256>>>();

    mlp1_kernel<<<dim3((BATCH * SEQ) / 64, MLPH / 64), 256>>>(b1);
    mlp2_kernel<<<(BATCH * SEQ) / 8, 256>>>(w2, b2, out);
}

// round 13
// speedup vs baseline: 1.9224x; 1.5670x over previous
#include <cuda_runtime.h>
#include <cuda_fp16.h>
#include <cstdint>
#include <math.h>

#define BATCH 256
#define SEQ   512
#define FEAT  26
#define HID   512
#define MLPH  256
#define NCLS  20
#define NBLK  128

// ---------------- device scratch (no allocations) ----------------
__device__ __half  g_hs[(size_t)BATCH * SEQ * HID];      // 128 MB fp16 hidden states
__device__ __half  g_hid_h[(size_t)BATCH * SEQ * MLPH];  // 64 MB  fp16 mlp hidden
__device__ __half  g_whh_h[4 * HID * HID];               // 2 MB
__device__ __half  g_wih_h[4 * HID * 32];                // 128 KB (K padded 26->32)
__device__ __half  g_w1_h[MLPH * HID];                   // 256 KB
__device__ __half  g_x_h[(size_t)BATCH * SEQ * 32];      // 8 MB (F padded 26->32)
__device__ float   g_bias[4 * HID];
__device__ unsigned g_cntv[4 * 32];                      // 4 barrier counters, 128B apart

// ---------------- fp16 mma (m16n8k16, fp32 accum) ----------------
__device__ __forceinline__ void mma_f16(float c[4],
                                        uint32_t a0, uint32_t a1, uint32_t a2, uint32_t a3,
                                        uint32_t b0, uint32_t b1) {
    asm volatile(
        "mma.sync.aligned.m16n8k16.row.col.f32.f16.f16.f32 "
        "{%0,%1,%2,%3},{%4,%5,%6,%7},{%8,%9},{%0,%1,%2,%3};\n"
        : "+f"(c[0]), "+f"(c[1]), "+f"(c[2]), "+f"(c[3])
        : "r"(a0), "r"(a1), "r"(a2), "r"(a3), "r"(b0), "r"(b1));
}

#define KP2 20   // words per 32-half row (padded; conflict-free fragment loads)

__device__ __forceinline__ unsigned ld_acquire(const unsigned* p) {
    unsigned v;
    asm volatile("ld.acquire.gpu.u32 %0, [%1];" : "=r"(v) : "l"(p) : "memory");
    return v;
}

__device__ __forceinline__ void cp_async16(uint32_t saddr, const void* gaddr) {
    asm volatile("cp.async.cg.shared.global [%0], [%1], 16;"
                 :: "r"(saddr), "l"(gaddr));
}
#define CP_COMMIT() asm volatile("cp.async.commit_group;" ::: "memory")
#define CP_WAIT(n)  asm volatile("cp.async.wait_group %0;" :: "n"(n) : "memory")

// fast nonlinearities (clamped; ~1e-6 abs error)
__device__ __forceinline__ float sigm(float x) {
    x = fminf(fmaxf(x, -30.f), 30.f);
    return __fdividef(1.0f, 1.0f + __expf(-x));
}
__device__ __forceinline__ float tanh_f(float x) {
    x = fminf(fmaxf(x, -15.f), 15.f);
    float e = __expf(-2.0f * x);
    return __fdividef(1.0f - e, 1.0f + e);
}

// one 32-half K chunk of MMAs: block tile 64x64, 8 warps = 4(m) x 2(n)
__device__ __forceinline__ void mma_chunk(float acc[4][4],
                                          const uint32_t* __restrict__ A,
                                          const uint32_t* __restrict__ B,
                                          int wm, int wn, int lane) {
    const int g  = lane >> 2;
    const int tg = lane & 3;
#pragma unroll
    for (int s = 0; s < 2; s++) {
        const int kk = s * 8 + tg;
        const int ar = wm * 16 + g;
        uint32_t a0 = A[ar * KP2 + kk];
        uint32_t a1 = A[(ar + 8) * KP2 + kk];
        uint32_t a2 = A[ar * KP2 + kk + 4];
        uint32_t a3 = A[(ar + 8) * KP2 + kk + 4];
#pragma unroll
        for (int nn = 0; nn < 4; nn++) {
            const int br = wn * 32 + nn * 8 + g;
            mma_f16(acc[nn], a0, a1, a2, a3, B[br * KP2 + kk], B[br * KP2 + kk + 4]);
        }
    }
}

// ---------------- prep ----------------
__global__ void prep_kernel(const float* __restrict__ w_ih, const float* __restrict__ w_hh,
                            const float* __restrict__ b_ih, const float* __restrict__ b_hh,
                            const float* __restrict__ w1) {
    long i = (long)blockIdx.x * blockDim.x + threadIdx.x;
    if (i < (long)4 * HID * HID) g_whh_h[i] = __float2half_rn(w_hh[i]);
    if (i < (long)MLPH * HID)    g_w1_h[i]  = __float2half_rn(w1[i]);
    if (i < (long)4 * HID * 32) {
        int r = (int)(i >> 5), c = (int)(i & 31);
        g_wih_h[i] = __float2half_rn(c < FEAT ? w_ih[r * FEAT + c] : 0.0f);
    }
    if (i < 4 * HID) g_bias[i] = b_ih[i] + b_hh[i];
    if (i < 4 * 32) g_cntv[i] = 0u;
}

__global__ void prepx_kernel(const float* __restrict__ x) {
    long i = (long)blockIdx.x * blockDim.x + threadIdx.x;
    if (i < (long)BATCH * SEQ * 32) {
        long bs = i >> 5;
        int  c  = (int)(i & 31);
        g_x_h[i] = __float2half_rn(c < FEAT ? x[bs * FEAT + c] : 0.0f);
    }
}

// ---------------- persistent LSTM ----------------
// 128 blocks = 4 batch-tiles x 32 unit-tiles. Weights resident in smem.
// Per step: 4-stage cp.async pipeline streams h (and x) chunks.
__global__ void __launch_bounds__(256, 1) lstm_persist_kernel() {
    extern __shared__ uint32_t dsm[];
    uint32_t* Bw = dsm;                       // 17*64*KP2 words (whh chunks 0..15, wih = 16)
    uint32_t* Aq = dsm + 17 * 64 * KP2;       // 4 stages * 64 * KP2
    __shared__ float zs[64][68];
    __shared__ float bsm[64];

    const int tid  = threadIdx.x;
    const int lane = tid & 31;
    const int warp = tid >> 5;
    const int wm   = warp >> 1;
    const int wn   = warp & 1;
    const int blk  = blockIdx.x;
    const int mb   = blk & 3;
    const int m0   = mb * 64;
    const int u0   = (blk >> 2) * 16;

    const int r0 = tid >> 2;                       // tile row 0..63
    const int sg = tid & 3;                        // 8-half segment
    const int ng = (r0 >> 4) * HID + u0 + (r0 & 15);  // weight row: gate*H + unit

    // --- load resident weight tiles (once) ---
#pragma unroll
    for (int kc = 0; kc < 17; kc++) {
        int4 v;
        if (kc < 16)
            v = *reinterpret_cast<const int4*>(g_whh_h + (long)ng * HID + kc * 32 + sg * 8);
        else
            v = *reinterpret_cast<const int4*>(g_wih_h + ng * 32 + sg * 8);
        *reinterpret_cast<int4*>(&Bw[(kc * 64 + r0) * KP2 + sg * 4]) = v;
    }
    if (tid < 64) bsm[tid] = g_bias[(tid >> 4) * HID + u0 + (tid & 15)];
    __syncthreads();

    uint32_t aq_base;
    {
        size_t a = __cvta_generic_to_shared(Aq);
        aq_base = (uint32_t)a;
    }

    // cell state in registers: thread owns (batch bl, units jj0..jj0+3)
    const int bl  = tid >> 2;
    const int jj0 = (tid & 3) * 4;
    float creg[4] = {0.f, 0.f, 0.f, 0.f};

    unsigned target = 0;
    unsigned* cnt = &g_cntv[mb * 32];

    for (int t = 0; t < SEQ; t++) {
        float acc[4][4];
#pragma unroll
        for (int i = 0; i < 4; i++)
#pragma unroll
            for (int j = 0; j < 4; j++) acc[i][j] = 0.0f;

        const int nch  = (t == 0) ? 1 : 17;
        const int base = (t == 0) ? 16 : 0;

        // A chunk source address
        const __half* hrow = g_hs + ((long)(m0 + r0) * SEQ + (t - 1)) * HID + sg * 8;
        const __half* xrow = g_x_h + ((long)(m0 + r0) * SEQ + t) * 32 + sg * 8;

        // prologue: 3 chunks in flight
        const int npro = (nch < 3) ? nch : 3;
        for (int k = 0; k < npro; k++) {
            const int kc = base + k;
            const void* src = (kc < 16) ? (const void*)(hrow + kc * 32) : (const void*)xrow;
            cp_async16(aq_base + ((k & 3) * 64 * KP2 + r0 * KP2 + sg * 4) * 4, src);
            CP_COMMIT();
        }

        for (int ci = 0; ci < nch; ci++) {
            const int rem = nch - 1 - ci;
            if (rem >= 2)      CP_WAIT(2);
            else if (rem == 1) CP_WAIT(1);
            else               CP_WAIT(0);
            __syncthreads();
            if (ci + 3 < nch) {
                const int kc = base + ci + 3;
                const void* src = (kc < 16) ? (const void*)(hrow + kc * 32) : (const void*)xrow;
                cp_async16(aq_base + (((ci + 3) & 3) * 64 * KP2 + r0 * KP2 + sg * 4) * 4, src);
                CP_COMMIT();
            }
            mma_chunk(acc, Aq + (ci & 3) * 64 * KP2, Bw + (base + ci) * 64 * KP2,
                      wm, wn, lane);
        }
        __syncthreads();

        // stage z tile
        {
            const int row = wm * 16 + (lane >> 2);
            const int cq  = 2 * (lane & 3);
#pragma unroll
            for (int nn = 0; nn < 4; nn++) {
                const int col = wn * 32 + nn * 8 + cq;
                zs[row][col]         = acc[nn][0];
                zs[row][col + 1]     = acc[nn][1];
                zs[row + 8][col]     = acc[nn][2];
                zs[row + 8][col + 1] = acc[nn][3];
            }
        }
        __syncthreads();

        // gate update (c in registers), store h fp16
        {
            float ho[4];
#pragma unroll
            for (int i = 0; i < 4; i++) {
                const int jj = jj0 + i;
                float zi = zs[bl][jj]      + bsm[jj];
                float zf = zs[bl][16 + jj] + bsm[16 + jj];
                float zg = zs[bl][32 + jj] + bsm[32 + jj];
                float zo = zs[bl][48 + jj] + bsm[48 + jj];
                float cn = sigm(zf) * creg[i] + sigm(zi) * tanh_f(zg);
                creg[i]  = cn;
                ho[i]    = sigm(zo) * tanh_f(cn);
            }
            __half2 p0 = __floats2half2_rn(ho[0], ho[1]);
            __half2 p1 = __floats2half2_rn(ho[2], ho[3]);
            uint2 v;
            v.x = *reinterpret_cast<uint32_t*>(&p0);
            v.y = *reinterpret_cast<uint32_t*>(&p1);
            *reinterpret_cast<uint2*>(
                g_hs + ((long)(m0 + bl) * SEQ + t) * HID + u0 + jj0) = v;
        }

        // group barrier (32 blocks sharing batch-tile mb)
        __threadfence();
        __syncthreads();
        if (tid == 0) {
            atomicAdd(cnt, 1u);
            target += 32;
            while (ld_acquire(cnt) < target) {}
        }
        __syncthreads();
    }
}

// ---------------- MLP layer 1: hid = relu(hs @ w1^T + b1), fp16 out ----------------
// grid (4 n-tiles, 2048 row-tiles): co-resident blocks share A rows via L2.
__global__ void __launch_bounds__(256, 1) mlp1_kernel(const float* __restrict__ b1) {
    __shared__ uint32_t As[2][64][KP2];
    __shared__ uint32_t Bs[2][64][KP2];

    const int tid  = threadIdx.x;
    const int lane = tid & 31;
    const int warp = tid >> 5;
    const int wm   = warp >> 1;
    const int wn   = warp & 1;
    const int  n0   = blockIdx.x * 64;
    const long row0 = (long)blockIdx.y * 64;

    const int r0 = tid >> 2;
    const int sg = tid & 3;

    float acc[4][4];
#pragma unroll
    for (int i = 0; i < 4; i++)
#pragma unroll
        for (int j = 0; j < 4; j++) acc[i][j] = 0.0f;

    int4 aR = *reinterpret_cast<const int4*>(g_hs + (row0 + r0) * HID + sg * 8);
    int4 bR = *reinterpret_cast<const int4*>(g_w1_h + (long)(n0 + r0) * HID + sg * 8);
    *reinterpret_cast<int4*>(&As[0][r0][sg * 4]) = aR;
    *reinterpret_cast<int4*>(&Bs[0][r0][sg * 4]) = bR;
    __syncthreads();

    const int NCH = HID / 32;  // 16
    for (int kc = 0; kc < NCH; kc++) {
        if (kc + 1 < NCH) {
            aR = *reinterpret_cast<const int4*>(
                     g_hs + (row0 + r0) * HID + (kc + 1) * 32 + sg * 8);
            bR = *reinterpret_cast<const int4*>(
                     g_w1_h + (long)(n0 + r0) * HID + (kc + 1) * 32 + sg * 8);
        }
        mma_chunk(acc, &As[kc & 1][0][0], &Bs[kc & 1][0][0], wm, wn, lane);
        if (kc + 1 < NCH) {
            const int nb = (kc + 1) & 1;
            __syncthreads();
            *reinterpret_cast<int4*>(&As[nb][r0][sg * 4]) = aR;
            *reinterpret_cast<int4*>(&Bs[nb][r0][sg * 4]) = bR;
            __syncthreads();
        }
    }

    // epilogue: +b1, relu, fp16 store
    {
        const int cq = 2 * (lane & 3);
        const long rr = row0 + wm * 16 + (lane >> 2);
#pragma unroll
        for (int nn = 0; nn < 4; nn++) {
            const int col = n0 + wn * 32 + nn * 8 + cq;
            float bb0 = b1[col], bb1 = b1[col + 1];
            __half2 v0 = __floats2half2_rn(fmaxf(acc[nn][0] + bb0, 0.0f),
                                           fmaxf(acc[nn][1] + bb1, 0.0f));
            __half2 v1 = __floats2half2_rn(fmaxf(acc[nn][2] + bb0, 0.0f),
                                           fmaxf(acc[nn][3] + bb1, 0.0f));
            *reinterpret_cast<__half2*>(g_hid_h + rr * MLPH + col)       = v0;
            *reinterpret_cast<__half2*>(g_hid_h + (rr + 8) * MLPH + col) = v1;
        }
    }
}

// ---------------- MLP layer 2 + log_softmax ----------------
__global__ void __launch_bounds__(256, 2)
mlp2_kernel(const float* __restrict__ w2, const float* __restrict__ b2,
            float* __restrict__ out) {
    __shared__ float w2s[NCLS][MLPH + 1];
    __shared__ float hr[8][MLPH];

    const int tid  = threadIdx.x;
    const int lane = tid & 31;
    const int warp = tid >> 5;

    for (int e = tid; e < NCLS * MLPH; e += 256)
        w2s[e / MLPH][e % MLPH] = w2[e];

    const long row = (long)blockIdx.x * 8 + warp;
    for (int k = lane; k < MLPH; k += 32)
        hr[warp][k] = __half2float(g_hid_h[row * MLPH + k]);
    __syncthreads();

    float logit = -1e30f;
    if (lane < NCLS) {
        float s = b2[lane];
#pragma unroll 8
        for (int k = 0; k < MLPH; k++)
            s += hr[warp][k] * w2s[lane][k];
        logit = s;
    }
    float m = logit;
#pragma unroll
    for (int o = 16; o; o >>= 1) m = fmaxf(m, __shfl_xor_sync(0xffffffffu, m, o));
    float e = (lane < NCLS) ? expf(logit - m) : 0.0f;
    float ssum = e;
#pragma unroll
    for (int o = 16; o; o >>= 1) ssum += __shfl_xor_sync(0xffffffffu, ssum, o);
    if (lane < NCLS)
        out[row * NCLS + lane] = logit - m - logf(ssum);
}

// ---------------- launch ----------------
extern "C" void kernel_launch(void* const* d_in, const int* in_sizes, int n_in,
                              void* d_out, int out_size) {
    const float* x    = (const float*)d_in[0];
    const float* w_ih = (const float*)d_in[1];
    const float* w_hh = (const float*)d_in[2];
    const float* b_ih = (const float*)d_in[3];
    const float* b_hh = (const float*)d_in[4];
    const float* w1   = (const float*)d_in[5];
    const float* b1   = (const float*)d_in[6];
    const float* w2   = (const float*)d_in[7];
    const float* b2   = (const float*)d_in[8];
    float* out = (float*)d_out;

    prep_kernel<<<(4 * HID * HID + 255) / 256, 256>>>(w_ih, w_hh, b_ih, b_hh, w1);
    prepx_kernel<<<((long)BATCH * SEQ * 32 + 255) / 256, 256>>>(x);

    const int DSMEM = (17 * 64 * KP2 + 4 * 64 * KP2) * 4;  // 107,520 B
    cudaFuncSetAttribute(lstm_persist_kernel,
                         cudaFuncAttributeMaxDynamicSharedMemorySize, DSMEM);
    lstm_persist_kernel<<<NBLK, 256, DSMEM>>>();

    mlp1_kernel<<<dim3(MLPH / 64, (BATCH * SEQ) / 64), 256>>>(b1);
    mlp2_kernel<<<(BATCH * SEQ) / 8, 256>>>(w2, b2, out);
}

// round 15
// speedup vs baseline: 2.0115x; 1.0464x over previous
#include <cuda_runtime.h>
#include <cuda_fp16.h>
#include <cstdint>
#include <math.h>

#define BATCH 256
#define SEQ   512
#define FEAT  26
#define HID   512
#define MLPH  256
#define NCLS  20
#define NBLK  128

// ---------------- device scratch (no allocations) ----------------
__device__ __half  g_hs[(size_t)BATCH * SEQ * HID];      // 128 MB fp16 hidden states
__device__ __half  g_hid_h[(size_t)BATCH * SEQ * MLPH];  // 64 MB  fp16 mlp hidden
__device__ __half  g_whh_h[4 * HID * HID];               // 2 MB
__device__ __half  g_wih_h[4 * HID * 32];                // 128 KB (K padded 26->32)
__device__ __half  g_w1_h[MLPH * HID];                   // 256 KB
__device__ __half  g_x_h[(size_t)BATCH * SEQ * 32];      // 8 MB (F padded 26->32)
__device__ float   g_bias[4 * HID];
__device__ unsigned g_cntv[4 * 32];                      // 4 barrier counters, 128B apart

// ---------------- mma / ldmatrix helpers ----------------
__device__ __forceinline__ void mma_f16_frag(float c[4],
                                             uint32_t a0, uint32_t a1, uint32_t a2, uint32_t a3,
                                             uint32_t b0, uint32_t b1) {
    asm volatile(
        "mma.sync.aligned.m16n8k16.row.col.f32.f16.f16.f32 "
        "{%0,%1,%2,%3},{%4,%5,%6,%7},{%8,%9},{%0,%1,%2,%3};\n"
        : "+f"(c[0]), "+f"(c[1]), "+f"(c[2]), "+f"(c[3])
        : "r"(a0), "r"(a1), "r"(a2), "r"(a3), "r"(b0), "r"(b1));
}

__device__ __forceinline__ void ldsm_x4(uint32_t& r0, uint32_t& r1,
                                        uint32_t& r2, uint32_t& r3, uint32_t addr) {
    asm volatile("ldmatrix.sync.aligned.m8n8.x4.shared.b16 {%0,%1,%2,%3}, [%4];"
                 : "=r"(r0), "=r"(r1), "=r"(r2), "=r"(r3) : "r"(addr));
}

#define KP2 20   // words per 32-half row (padded; conflict-free LDS/LDSM)

__device__ __forceinline__ uint32_t smem_u32(const void* p) {
    uint32_t a;
    asm("{ .reg .u64 t; cvta.to.shared.u64 t, %1; cvt.u32.u64 %0, t; }"
        : "=r"(a) : "l"(p));
    return a;
}
__device__ __forceinline__ unsigned ld_acquire(const unsigned* p) {
    unsigned v;
    asm volatile("ld.acquire.gpu.u32 %0, [%1];" : "=r"(v) : "l"(p) : "memory");
    return v;
}
__device__ __forceinline__ void cp_async16(uint32_t saddr, const void* gaddr) {
    asm volatile("cp.async.cg.shared.global [%0], [%1], 16;" :: "r"(saddr), "l"(gaddr));
}
#define CP_COMMIT() asm volatile("cp.async.commit_group;" ::: "memory")
#define CP_WAIT(n)  asm volatile("cp.async.wait_group %0;" :: "n"(n) : "memory")

// fast nonlinearities via MUFU.TANH
__device__ __forceinline__ float tanha(float x) {
    float y;
    asm("tanh.approx.f32 %0, %1;" : "=f"(y) : "f"(x));
    return y;
}
__device__ __forceinline__ float sigm(float x) {
    return 0.5f * tanha(0.5f * x) + 0.5f;
}

// 32x32 warp tile, one 32-half K chunk, fragments via ldmatrix.x4.
// aAddr/bAddr are lane-adjusted byte addresses into [64][KP2] word tiles.
__device__ __forceinline__ void mma_chunk32(float acc[2][4][4],
                                            uint32_t aAddr, uint32_t bAddr) {
#pragma unroll
    for (int s = 0; s < 2; s++) {
        uint32_t a[2][4];
#pragma unroll
        for (int mb = 0; mb < 2; mb++)
            ldsm_x4(a[mb][0], a[mb][1], a[mb][2], a[mb][3],
                    aAddr + (uint32_t)((mb * 16 * KP2 + s * 8) * 4));
        uint32_t b[4][2];
#pragma unroll
        for (int p = 0; p < 2; p++) {
            uint32_t r0, r1, r2, r3;
            ldsm_x4(r0, r1, r2, r3, bAddr + (uint32_t)((p * 16 * KP2 + s * 8) * 4));
            b[2 * p][0] = r0; b[2 * p][1] = r1;
            b[2 * p + 1][0] = r2; b[2 * p + 1][1] = r3;
        }
#pragma unroll
        for (int mb = 0; mb < 2; mb++)
#pragma unroll
            for (int nb = 0; nb < 4; nb++)
                mma_f16_frag(acc[mb][nb], a[mb][0], a[mb][1], a[mb][2], a[mb][3],
                             b[nb][0], b[nb][1]);
    }
}

// 16x32 warp tile chunk (mlp1, unchanged manual loads — proven path)
__device__ __forceinline__ void mma_chunk(float acc[4][4],
                                          const uint32_t* __restrict__ A,
                                          const uint32_t* __restrict__ B,
                                          int wm, int wn, int lane) {
    const int g  = lane >> 2;
    const int tg = lane & 3;
#pragma unroll
    for (int s = 0; s < 2; s++) {
        const int kk = s * 8 + tg;
        const int ar = wm * 16 + g;
        uint32_t a0 = A[ar * KP2 + kk];
        uint32_t a1 = A[(ar + 8) * KP2 + kk];
        uint32_t a2 = A[ar * KP2 + kk + 4];
        uint32_t a3 = A[(ar + 8) * KP2 + kk + 4];
#pragma unroll
        for (int nn = 0; nn < 4; nn++) {
            const int br = wn * 32 + nn * 8 + g;
            mma_f16_frag(acc[nn], a0, a1, a2, a3, B[br * KP2 + kk], B[br * KP2 + kk + 4]);
        }
    }
}

// ---------------- prep ----------------
__global__ void prep_kernel(const float* __restrict__ w_ih, const float* __restrict__ w_hh,
                            const float* __restrict__ b_ih, const float* __restrict__ b_hh,
                            const float* __restrict__ w1) {
    long i = (long)blockIdx.x * blockDim.x + threadIdx.x;
    if (i < (long)4 * HID * HID) g_whh_h[i] = __float2half_rn(w_hh[i]);
    if (i < (long)MLPH * HID)    g_w1_h[i]  = __float2half_rn(w1[i]);
    if (i < (long)4 * HID * 32) {
        int r = (int)(i >> 5), c = (int)(i & 31);
        g_wih_h[i] = __float2half_rn(c < FEAT ? w_ih[r * FEAT + c] : 0.0f);
    }
    if (i < 4 * HID) g_bias[i] = b_ih[i] + b_hh[i];
    if (i < 4 * 32) g_cntv[i] = 0u;
}

__global__ void prepx_kernel(const float* __restrict__ x) {
    long i = (long)blockIdx.x * blockDim.x + threadIdx.x;
    if (i < (long)BATCH * SEQ * 32) {
        long bs = i >> 5;
        int  c  = (int)(i & 31);
        g_x_h[i] = __float2half_rn(c < FEAT ? x[bs * FEAT + c] : 0.0f);
    }
}

// ---------------- persistent LSTM ----------------
// 128 blocks = 4 batch-tiles x 32 unit-tiles. Weights resident in smem.
// 8 warps = 2 k-groups x (2m x 2n) 32x32 warp tiles; k-groups own alternating
// K-chunks with private accumulators, merged through zs once per step.
__global__ void __launch_bounds__(256, 1) lstm_persist_kernel() {
    extern __shared__ uint32_t dsm[];
    uint32_t* Bw = dsm;                       // 17*64*KP2 (whh chunks 0..15, wih = 16)
    uint32_t* Aq = dsm + 17 * 64 * KP2;       // 4 stages * 64 * KP2
    __shared__ float zs[64][68];
    __shared__ float bsm[64];

    const int tid  = threadIdx.x;
    const int lane = tid & 31;
    const int warp = tid >> 5;
    const int wq   = warp & 3;
    const int kg   = warp >> 2;               // k-group 0/1
    const int wmoff = (wq >> 1) * 32;
    const int wnoff = (wq & 1) * 32;
    const int blk  = blockIdx.x;
    const int mb   = blk & 3;
    const int m0   = mb * 64;
    const int u0   = (blk >> 2) * 16;

    const int r0 = tid >> 2;                       // load row 0..63
    const int sg = tid & 3;                        // 8-half segment
    const int ng = (r0 >> 4) * HID + u0 + (r0 & 15);  // weight row: gate*H + unit

    // --- resident weight tiles (once) ---
#pragma unroll
    for (int kc = 0; kc < 17; kc++) {
        int4 v;
        if (kc < 16)
            v = *reinterpret_cast<const int4*>(g_whh_h + (long)ng * HID + kc * 32 + sg * 8);
        else
            v = *reinterpret_cast<const int4*>(g_wih_h + ng * 32 + sg * 8);
        *reinterpret_cast<int4*>(&Bw[(kc * 64 + r0) * KP2 + sg * 4]) = v;
    }
    if (tid < 64) bsm[tid] = g_bias[(tid >> 4) * HID + u0 + (tid & 15)];
    __syncthreads();

    const uint32_t aq_base = smem_u32(Aq);
    const uint32_t bw_base = smem_u32(Bw);

    // lane-invariant ldmatrix address offsets (bytes)
    const uint32_t laneA =
        (uint32_t)(((wmoff + (lane & 7) + ((lane >> 3) & 1) * 8) * KP2 +
                    (lane >> 4) * 4) * 4);
    const uint32_t laneB =
        (uint32_t)(((wnoff + (lane >> 4) * 8 + (lane & 7)) * KP2 +
                    ((lane >> 3) & 1) * 4) * 4);

    // cell state in registers: thread owns (batch bl, units jj0..jj0+3)
    const int bl  = tid >> 2;
    const int jj0 = (tid & 3) * 4;
    float creg[4] = {0.f, 0.f, 0.f, 0.f};

    unsigned target = 0;
    unsigned* cnt = &g_cntv[mb * 32];

    for (int t = 0; t < SEQ; t++) {
        float acc[2][4][4];
#pragma unroll
        for (int i = 0; i < 2; i++)
#pragma unroll
            for (int j = 0; j < 4; j++)
#pragma unroll
                for (int k = 0; k < 4; k++) acc[i][j][k] = 0.0f;

        const int nch  = (t == 0) ? 1 : 17;
        const int base = (t == 0) ? 16 : 0;

        const __half* hrow = g_hs + ((long)(m0 + r0) * SEQ + (t - 1)) * HID + sg * 8;
        const __half* xrow = g_x_h + ((long)(m0 + r0) * SEQ + t) * 32 + sg * 8;

        // prologue: 3 chunks in flight
        const int npro = (nch < 3) ? nch : 3;
        for (int k = 0; k < npro; k++) {
            const int kc = base + k;
            const void* src = (kc < 16) ? (const void*)(hrow + kc * 32) : (const void*)xrow;
            cp_async16(aq_base + ((k & 3) * 64 * KP2 + r0 * KP2 + sg * 4) * 4, src);
            CP_COMMIT();
        }

        for (int ci = 0; ci < nch; ci++) {
            const int rem = nch - 1 - ci;
            if (rem >= 2)      CP_WAIT(2);
            else if (rem == 1) CP_WAIT(1);
            else               CP_WAIT(0);
            __syncthreads();
            if (ci + 3 < nch) {
                const int kc = base + ci + 3;
                const void* src = (kc < 16) ? (const void*)(hrow + kc * 32) : (const void*)xrow;
                cp_async16(aq_base + (((ci + 3) & 3) * 64 * KP2 + r0 * KP2 + sg * 4) * 4, src);
                CP_COMMIT();
            }
            const int chunk = base + ci;
            if ((chunk & 1) == kg) {   // owner k-group does this chunk
                mma_chunk32(acc,
                            aq_base + (uint32_t)((ci & 3) * 64 * KP2 * 4) + laneA,
                            bw_base + (uint32_t)(chunk * 64 * KP2 * 4) + laneB);
            }
        }
        __syncthreads();  // all LDSM of last chunks done; zs merge begins

        // merge: kg1 stores acc, kg0 adds its acc on top
        if (kg == 1) {
#pragma unroll
            for (int mbi = 0; mbi < 2; mbi++)
#pragma unroll
                for (int nb = 0; nb < 4; nb++) {
                    const int row = wmoff + mbi * 16 + (lane >> 2);
                    const int col = wnoff + nb * 8 + 2 * (lane & 3);
                    *reinterpret_cast<float2*>(&zs[row][col]) =
                        make_float2(acc[mbi][nb][0], acc[mbi][nb][1]);
                    *reinterpret_cast<float2*>(&zs[row + 8][col]) =
                        make_float2(acc[mbi][nb][2], acc[mbi][nb][3]);
                }
        }
        __syncthreads();
        if (kg == 0) {
#pragma unroll
            for (int mbi = 0; mbi < 2; mbi++)
#pragma unroll
                for (int nb = 0; nb < 4; nb++) {
                    const int row = wmoff + mbi * 16 + (lane >> 2);
                    const int col = wnoff + nb * 8 + 2 * (lane & 3);
                    float2 v0 = *reinterpret_cast<float2*>(&zs[row][col]);
                    float2 v1 = *reinterpret_cast<float2*>(&zs[row + 8][col]);
                    v0.x += acc[mbi][nb][0]; v0.y += acc[mbi][nb][1];
                    v1.x += acc[mbi][nb][2]; v1.y += acc[mbi][nb][3];
                    *reinterpret_cast<float2*>(&zs[row][col])     = v0;
                    *reinterpret_cast<float2*>(&zs[row + 8][col]) = v1;
                }
        }
        __syncthreads();

        // gate update (c in registers), store h fp16
        {
            float ho[4];
#pragma unroll
            for (int i = 0; i < 4; i++) {
                const int jj = jj0 + i;
                float zi = zs[bl][jj]      + bsm[jj];
                float zf = zs[bl][16 + jj] + bsm[16 + jj];
                float zg = zs[bl][32 + jj] + bsm[32 + jj];
                float zo = zs[bl][48 + jj] + bsm[48 + jj];
                float cn = sigm(zf) * creg[i] + sigm(zi) * tanha(zg);
                creg[i]  = cn;
                ho[i]    = sigm(zo) * tanha(cn);
            }
            __half2 p0 = __floats2half2_rn(ho[0], ho[1]);
            __half2 p1 = __floats2half2_rn(ho[2], ho[3]);
            uint2 v;
            v.x = *reinterpret_cast<uint32_t*>(&p0);
            v.y = *reinterpret_cast<uint32_t*>(&p1);
            *reinterpret_cast<uint2*>(
                g_hs + ((long)(m0 + bl) * SEQ + t) * HID + u0 + jj0) = v;
        }

        // group barrier (32 blocks sharing batch-tile mb)
        __threadfence();
        __syncthreads();
        if (tid == 0) {
            atomicAdd(cnt, 1u);
            target += 32;
            while (ld_acquire(cnt) < target) {}
        }
        __syncthreads();
    }
}

// ---------------- MLP layer 1 (unchanged, proven) ----------------
__global__ void __launch_bounds__(256, 1) mlp1_kernel(const float* __restrict__ b1) {
    __shared__ uint32_t As[2][64][KP2];
    __shared__ uint32_t Bs[2][64][KP2];

    const int tid  = threadIdx.x;
    const int lane = tid & 31;
    const int warp = tid >> 5;
    const int wm   = warp >> 1;
    const int wn   = warp & 1;
    const int  n0   = blockIdx.x * 64;
    const long row0 = (long)blockIdx.y * 64;

    const int r0 = tid >> 2;
    const int sg = tid & 3;

    float acc[4][4];
#pragma unroll
    for (int i = 0; i < 4; i++)
#pragma unroll
        for (int j = 0; j < 4; j++) acc[i][j] = 0.0f;

    int4 aR = *reinterpret_cast<const int4*>(g_hs + (row0 + r0) * HID + sg * 8);
    int4 bR = *reinterpret_cast<const int4*>(g_w1_h + (long)(n0 + r0) * HID + sg * 8);
    *reinterpret_cast<int4*>(&As[0][r0][sg * 4]) = aR;
    *reinterpret_cast<int4*>(&Bs[0][r0][sg * 4]) = bR;
    __syncthreads();

    const int NCH = HID / 32;
    for (int kc = 0; kc < NCH; kc++) {
        if (kc + 1 < NCH) {
            aR = *reinterpret_cast<const int4*>(
                     g_hs + (row0 + r0) * HID + (kc + 1) * 32 + sg * 8);
            bR = *reinterpret_cast<const int4*>(
                     g_w1_h + (long)(n0 + r0) * HID + (kc + 1) * 32 + sg * 8);
        }
        mma_chunk(acc, &As[kc & 1][0][0], &Bs[kc & 1][0][0], wm, wn, lane);
        if (kc + 1 < NCH) {
            const int nb = (kc + 1) & 1;
            __syncthreads();
            *reinterpret_cast<int4*>(&As[nb][r0][sg * 4]) = aR;
            *reinterpret_cast<int4*>(&Bs[nb][r0][sg * 4]) = bR;
            __syncthreads();
        }
    }

    {
        const int cq = 2 * (lane & 3);
        const long rr = row0 + wm * 16 + (lane >> 2);
#pragma unroll
        for (int nn = 0; nn < 4; nn++) {
            const int col = n0 + wn * 32 + nn * 8 + cq;
            float bb0 = b1[col], bb1 = b1[col + 1];
            __half2 v0 = __floats2half2_rn(fmaxf(acc[nn][0] + bb0, 0.0f),
                                           fmaxf(acc[nn][1] + bb1, 0.0f));
            __half2 v1 = __floats2half2_rn(fmaxf(acc[nn][2] + bb0, 0.0f),
                                           fmaxf(acc[nn][3] + bb1, 0.0f));
            *reinterpret_cast<__half2*>(g_hid_h + rr * MLPH + col)       = v0;
            *reinterpret_cast<__half2*>(g_hid_h + (rr + 8) * MLPH + col) = v1;
        }
    }
}

// ---------------- MLP layer 2 + log_softmax ----------------
__global__ void __launch_bounds__(256, 2)
mlp2_kernel(const float* __restrict__ w2, const float* __restrict__ b2,
            float* __restrict__ out) {
    __shared__ float w2s[NCLS][MLPH + 1];
    __shared__ float hr[8][MLPH];

    const int tid  = threadIdx.x;
    const int lane = tid & 31;
    const int warp = tid >> 5;

    for (int e = tid; e < NCLS * MLPH; e += 256)
        w2s[e / MLPH][e % MLPH] = w2[e];

    const long row = (long)blockIdx.x * 8 + warp;
    for (int k = lane; k < MLPH; k += 32)
        hr[warp][k] = __half2float(g_hid_h[row * MLPH + k]);
    __syncthreads();

    float logit = -1e30f;
    if (lane < NCLS) {
        float s = b2[lane];
#pragma unroll 8
        for (int k = 0; k < MLPH; k++)
            s += hr[warp][k] * w2s[lane][k];
        logit = s;
    }
    float m = logit;
#pragma unroll
    for (int o = 16; o; o >>= 1) m = fmaxf(m, __shfl_xor_sync(0xffffffffu, m, o));
    float e = (lane < NCLS) ? expf(logit - m) : 0.0f;
    float ssum = e;
#pragma unroll
    for (int o = 16; o; o >>= 1) ssum += __shfl_xor_sync(0xffffffffu, ssum, o);
    if (lane < NCLS)
        out[row * NCLS + lane] = logit - m - logf(ssum);
}

// ---------------- launch ----------------
extern "C" void kernel_launch(void* const* d_in, const int* in_sizes, int n_in,
                              void* d_out, int out_size) {
    const float* x    = (const float*)d_in[0];
    const float* w_ih = (const float*)d_in[1];
    const float* w_hh = (const float*)d_in[2];
    const float* b_ih = (const float*)d_in[3];
    const float* b_hh = (const float*)d_in[4];
    const float* w1   = (const float*)d_in[5];
    const float* b1   = (const float*)d_in[6];
    const float* w2   = (const float*)d_in[7];
    const float* b2   = (const float*)d_in[8];
    float* out = (float*)d_out;

    prep_kernel<<<(4 * HID * HID + 255) / 256, 256>>>(w_ih, w_hh, b_ih, b_hh, w1);
    prepx_kernel<<<((long)BATCH * SEQ * 32 + 255) / 256, 256>>>(x);

    const int DSMEM = (17 * 64 * KP2 + 4 * 64 * KP2) * 4;  // 107,520 B
    cudaFuncSetAttribute(lstm_persist_kernel,
                         cudaFuncAttributeMaxDynamicSharedMemorySize, DSMEM);
    lstm_persist_kernel<<<NBLK, 256, DSMEM>>>();

    mlp1_kernel<<<dim3(MLPH / 64, (BATCH * SEQ) / 64), 256>>>(b1);
    mlp2_kernel<<<(BATCH * SEQ) / 8, 256>>>(w2, b2, out);
}

// round 16
// speedup vs baseline: 2.3742x; 1.1803x over previous
#include <cuda_runtime.h>
#include <cuda_fp16.h>
#include <cstdint>
#include <math.h>

#define BATCH 256
#define SEQ   512
#define FEAT  26
#define HID   512
#define MLPH  256
#define NCLS  20
#define NBLK  128

// ---------------- device scratch (no allocations) ----------------
// g_hs is T-MAJOR: [t][b][HID]
__device__ __half  g_hs[(size_t)SEQ * BATCH * HID];      // 128 MB
__device__ __half  g_hid_h[(size_t)BATCH * SEQ * MLPH];  // 64 MB
__device__ __half  g_whh_h[4 * HID * HID];               // 2 MB
__device__ __half  g_wih_h[4 * HID * 64];                // 256 KB (K padded 26->64)
__device__ __half  g_w1_h[MLPH * HID];                   // 256 KB
__device__ __half  g_x_h[(size_t)BATCH * SEQ * 64];      // 16 MB (F padded 26->64)
__device__ float   g_bias[4 * HID];
__device__ unsigned g_cntv[4 * 32];                      // 4 group counters, 128B apart

// ---------------- asm helpers ----------------
__device__ __forceinline__ void mma_f16_frag(float c[4],
                                             uint32_t a0, uint32_t a1, uint32_t a2, uint32_t a3,
                                             uint32_t b0, uint32_t b1) {
    asm volatile(
        "mma.sync.aligned.m16n8k16.row.col.f32.f16.f16.f32 "
        "{%0,%1,%2,%3},{%4,%5,%6,%7},{%8,%9},{%0,%1,%2,%3};\n"
        : "+f"(c[0]), "+f"(c[1]), "+f"(c[2]), "+f"(c[3])
        : "r"(a0), "r"(a1), "r"(a2), "r"(a3), "r"(b0), "r"(b1));
}
__device__ __forceinline__ void ldsm_x4(uint32_t& r0, uint32_t& r1,
                                        uint32_t& r2, uint32_t& r3, uint32_t addr) {
    asm volatile("ldmatrix.sync.aligned.m8n8.x4.shared.b16 {%0,%1,%2,%3}, [%4];"
                 : "=r"(r0), "=r"(r1), "=r"(r2), "=r"(r3) : "r"(addr));
}
__device__ __forceinline__ uint32_t smem_u32(const void* p) {
    uint32_t a;
    asm("{ .reg .u64 t; cvta.to.shared.u64 t, %1; cvt.u32.u64 %0, t; }" : "=r"(a) : "l"(p));
    return a;
}
__device__ __forceinline__ unsigned ld_acquire(const unsigned* p) {
    unsigned v;
    asm volatile("ld.acquire.gpu.u32 %0, [%1];" : "=r"(v) : "l"(p) : "memory");
    return v;
}
__device__ __forceinline__ void red_release_add(unsigned* p, unsigned v) {
    asm volatile("red.release.gpu.global.add.u32 [%0], %1;" :: "l"(p), "r"(v) : "memory");
}
__device__ __forceinline__ void cp_async16(uint32_t saddr, const void* gaddr) {
    asm volatile("cp.async.cg.shared.global [%0], [%1], 16;" :: "r"(saddr), "l"(gaddr));
}
#define CP_COMMIT() asm volatile("cp.async.commit_group;" ::: "memory")
#define CP_WAIT(n)  asm volatile("cp.async.wait_group %0;" :: "n"(n) : "memory")

__device__ __forceinline__ float tanha(float x) {
    float y;
    asm("tanh.approx.f32 %0, %1;" : "=f"(y) : "f"(x));
    return y;
}
__device__ __forceinline__ float sigm(float x) { return 0.5f * tanha(0.5f * x) + 0.5f; }

// ---------------- LSTM tile geometry ----------------
// 9 chunks of K=64 (8 x w_hh + 1 x w_ih-padded). Row stride 36 words (conflict-free).
#define ROWW        36
#define CHUNK_WORDS (64 * ROWW)          // 2304
#define CHUNK_BYTES (CHUNK_WORDS * 4)    // 9216
#define NCH         9
#define DSMEM       (2 * NCH * CHUNK_BYTES)   // B: 9 chunks, A: 9 slots = 165,888 B

// 32x32 warp tile, one K=64 chunk (4 k16-steps), fragments via ldmatrix.x4.
__device__ __forceinline__ void mma_chunk64(float acc[2][4][4],
                                            uint32_t aAddr, uint32_t bAddr) {
#pragma unroll
    for (int s = 0; s < 4; s++) {
        uint32_t a[2][4];
#pragma unroll
        for (int mb = 0; mb < 2; mb++)
            ldsm_x4(a[mb][0], a[mb][1], a[mb][2], a[mb][3],
                    aAddr + (uint32_t)((mb * 16 * ROWW + s * 8) * 4));
        uint32_t b[4][2];
#pragma unroll
        for (int p = 0; p < 2; p++) {
            uint32_t r0, r1, r2, r3;
            ldsm_x4(r0, r1, r2, r3, bAddr + (uint32_t)((p * 16 * ROWW + s * 8) * 4));
            b[2 * p][0] = r0; b[2 * p][1] = r1;
            b[2 * p + 1][0] = r2; b[2 * p + 1][1] = r3;
        }
#pragma unroll
        for (int mb = 0; mb < 2; mb++)
#pragma unroll
            for (int nb = 0; nb < 4; nb++)
                mma_f16_frag(acc[mb][nb], a[mb][0], a[mb][1], a[mb][2], a[mb][3],
                             b[nb][0], b[nb][1]);
    }
}

// ---------------- prep ----------------
__global__ void prep_kernel(const float* __restrict__ w_ih, const float* __restrict__ w_hh,
                            const float* __restrict__ b_ih, const float* __restrict__ b_hh,
                            const float* __restrict__ w1) {
    long i = (long)blockIdx.x * blockDim.x + threadIdx.x;
    if (i < (long)4 * HID * HID) g_whh_h[i] = __float2half_rn(w_hh[i]);
    if (i < (long)MLPH * HID)    g_w1_h[i]  = __float2half_rn(w1[i]);
    if (i < (long)4 * HID * 64) {
        int r = (int)(i >> 6), c = (int)(i & 63);
        g_wih_h[i] = __float2half_rn(c < FEAT ? w_ih[r * FEAT + c] : 0.0f);
    }
    if (i < 4 * HID) g_bias[i] = b_ih[i] + b_hh[i];
    if (i < 4 * 32) g_cntv[i] = 0u;
}

__global__ void prepx_kernel(const float* __restrict__ x) {
    long i = (long)blockIdx.x * blockDim.x + threadIdx.x;
    if (i < (long)BATCH * SEQ * 64) {
        long bs = i >> 6;
        int  c  = (int)(i & 63);
        g_x_h[i] = __float2half_rn(c < FEAT ? x[bs * FEAT + c] : 0.0f);
    }
}

// ---------------- persistent LSTM ----------------
// 128 blocks = 4 batch-tiles x 32 unit-tiles. Weights + full A staging in SMEM.
// 8 warps = 2 k-groups x (2m x 2n) 32x32 warp tiles; chunk owner = chunk&1.
__global__ void __launch_bounds__(256, 1) lstm_persist_kernel() {
    extern __shared__ uint32_t dsm[];
    uint32_t* Bw = dsm;                        // 9 chunks x 64 x 36 words
    uint32_t* Aq = dsm + NCH * CHUNK_WORDS;    // 9 slots  x 64 x 36 words
    __shared__ float zs[64][68];
    __shared__ float bsm[64];

    const int tid  = threadIdx.x;
    const int lane = tid & 31;
    const int warp = tid >> 5;
    const int wq   = warp & 3;
    const int kg   = warp >> 2;                // k-group 0/1
    const int wmoff = (wq >> 1) * 32;
    const int wnoff = (wq & 1) * 32;
    const int blk  = blockIdx.x;
    const int mb   = blk & 3;
    const int m0   = mb * 64;
    const int u0   = (blk >> 2) * 16;

    const int r0 = tid >> 2;                   // load row 0..63
    const int sg = tid & 3;                    // 2 x 16B pieces per thread
    const int ng = (r0 >> 4) * HID + u0 + (r0 & 15);  // weight row: gate*H + unit

    // --- resident weight tiles (once): 64 rows x 9 chunks x 8 pieces ---
    for (int idx = tid; idx < 64 * 72; idx += 256) {
        const int row   = idx / 72;
        const int piece = idx - row * 72;
        const int ch    = piece >> 3;
        const int pc    = piece & 7;
        const int k     = ch * 64 + pc * 8;
        const int wr    = (row >> 4) * HID + u0 + (row & 15);
        int4 v;
        if (ch < 8) v = *reinterpret_cast<const int4*>(g_whh_h + (long)wr * HID + k);
        else        v = *reinterpret_cast<const int4*>(g_wih_h + (long)wr * 64 + (k - 512));
        *reinterpret_cast<int4*>(&Bw[ch * CHUNK_WORDS + row * ROWW + pc * 4]) = v;
    }
    if (tid < 64) bsm[tid] = g_bias[(tid >> 4) * HID + u0 + (tid & 15)];
    __syncthreads();

    const uint32_t aq_base = smem_u32(Aq);
    const uint32_t bw_base = smem_u32(Bw);

    // ldmatrix lane offsets (bytes), row stride 36 words
    const uint32_t laneA =
        (uint32_t)(((wmoff + (lane & 7) + ((lane >> 3) & 1) * 8) * ROWW +
                    (lane >> 4) * 4) * 4);
    const uint32_t laneB =
        (uint32_t)(((wnoff + (lane >> 4) * 8 + (lane & 7)) * ROWW +
                    ((lane >> 3) & 1) * 4) * 4);

    // cp.async dest offsets for this thread's two 16B pieces (within a chunk slot)
    const uint32_t dstp0 = (uint32_t)((r0 * ROWW + (sg * 2 + 0) * 4) * 4);
    const uint32_t dstp1 = (uint32_t)((r0 * ROWW + (sg * 2 + 1) * 4) * 4);

    // cell state in registers: thread owns (batch bl, units jj0..jj0+3)
    const int bl  = tid >> 2;
    const int jj0 = (tid & 3) * 4;
    float creg[4] = {0.f, 0.f, 0.f, 0.f};

    unsigned target = 0;
    unsigned* cnt = &g_cntv[mb * 32];

    const __half* xrowp = g_x_h + (long)(m0 + r0) * SEQ * 64;

    for (int t = 0; t < SEQ; t++) {
        float acc[2][4][4];
#pragma unroll
        for (int i = 0; i < 2; i++)
#pragma unroll
            for (int j = 0; j < 4; j++)
#pragma unroll
                for (int k = 0; k < 4; k++) acc[i][j][k] = 0.0f;

        // ---- issue x load (independent of h), group 0 ----
        {
            const __half* xs = xrowp + (long)t * 64;
            cp_async16(aq_base + 8 * CHUNK_BYTES + dstp0, xs + (sg * 2 + 0) * 8);
            cp_async16(aq_base + 8 * CHUNK_BYTES + dstp1, xs + (sg * 2 + 1) * 8);
            CP_COMMIT();
        }

        // ---- wait for h(t-1) to be published by all unit-tiles ----
        if (t > 0) {
            target += 32;
            if (tid == 0) { while (ld_acquire(cnt) < target) {} }
        }
        __syncthreads();

        // ---- issue all 8 h chunk loads (groups 1..8) ----
        if (t > 0) {
            const __half* hs = g_hs + ((long)(t - 1) * BATCH + (m0 + r0)) * HID;
#pragma unroll
            for (int c = 0; c < 8; c++) {
                cp_async16(aq_base + c * CHUNK_BYTES + dstp0, hs + c * 64 + (sg * 2 + 0) * 8);
                cp_async16(aq_base + c * CHUNK_BYTES + dstp1, hs + c * 64 + (sg * 2 + 1) * 8);
                CP_COMMIT();
            }
            CP_WAIT(8);   // x (group 0) complete
        } else {
            CP_WAIT(0);
        }
        __syncthreads();

        // ---- x chunk (chunk 8, owner kg0) ----
        if (kg == 0)
            mma_chunk64(acc, aq_base + 8 * CHUNK_BYTES + laneA,
                        bw_base + 8 * CHUNK_BYTES + laneB);

        // ---- h chunks 0..7, streaming waits ----
        if (t > 0) {
#define STEP_CHUNK(c, w)                                                     \
            CP_WAIT(w);                                                      \
            __syncthreads();                                                 \
            if (((c) & 1) == kg)                                             \
                mma_chunk64(acc, aq_base + (c) * CHUNK_BYTES + laneA,        \
                            bw_base + (c) * CHUNK_BYTES + laneB);
            STEP_CHUNK(0, 7) STEP_CHUNK(1, 6) STEP_CHUNK(2, 5) STEP_CHUNK(3, 4)
            STEP_CHUNK(4, 3) STEP_CHUNK(5, 2) STEP_CHUNK(6, 1) STEP_CHUNK(7, 0)
#undef STEP_CHUNK
        }
        __syncthreads();

        // ---- merge k-groups through zs ----
        if (kg == 1) {
#pragma unroll
            for (int mbi = 0; mbi < 2; mbi++)
#pragma unroll
                for (int nb = 0; nb < 4; nb++) {
                    const int row = wmoff + mbi * 16 + (lane >> 2);
                    const int col = wnoff + nb * 8 + 2 * (lane & 3);
                    *reinterpret_cast<float2*>(&zs[row][col]) =
                        make_float2(acc[mbi][nb][0], acc[mbi][nb][1]);
                    *reinterpret_cast<float2*>(&zs[row + 8][col]) =
                        make_float2(acc[mbi][nb][2], acc[mbi][nb][3]);
                }
        }
        __syncthreads();
        if (kg == 0) {
#pragma unroll
            for (int mbi = 0; mbi < 2; mbi++)
#pragma unroll
                for (int nb = 0; nb < 4; nb++) {
                    const int row = wmoff + mbi * 16 + (lane >> 2);
                    const int col = wnoff + nb * 8 + 2 * (lane & 3);
                    float2 v0 = *reinterpret_cast<float2*>(&zs[row][col]);
                    float2 v1 = *reinterpret_cast<float2*>(&zs[row + 8][col]);
                    v0.x += acc[mbi][nb][0]; v0.y += acc[mbi][nb][1];
                    v1.x += acc[mbi][nb][2]; v1.y += acc[mbi][nb][3];
                    *reinterpret_cast<float2*>(&zs[row][col])     = v0;
                    *reinterpret_cast<float2*>(&zs[row + 8][col]) = v1;
                }
        }
        __syncthreads();

        // ---- gate update (c in registers), store h fp16 (t-major) ----
        {
            float ho[4];
#pragma unroll
            for (int i = 0; i < 4; i++) {
                const int jj = jj0 + i;
                float zi = zs[bl][jj]      + bsm[jj];
                float zf = zs[bl][16 + jj] + bsm[16 + jj];
                float zg = zs[bl][32 + jj] + bsm[32 + jj];
                float zo = zs[bl][48 + jj] + bsm[48 + jj];
                float cn = sigm(zf) * creg[i] + sigm(zi) * tanha(zg);
                creg[i]  = cn;
                ho[i]    = sigm(zo) * tanha(cn);
            }
            __half2 p0 = __floats2half2_rn(ho[0], ho[1]);
            __half2 p1 = __floats2half2_rn(ho[2], ho[3]);
            uint2 v;
            v.x = *reinterpret_cast<uint32_t*>(&p0);
            v.y = *reinterpret_cast<uint32_t*>(&p1);
            *reinterpret_cast<uint2*>(
                g_hs + ((long)t * BATCH + (m0 + bl)) * HID + u0 + jj0) = v;
        }

        // ---- arrive (release): publish h(t) ----
        __syncthreads();
        if (tid == 0) red_release_add(cnt, 1u);
    }
}

// ---------------- MLP layer 1 (proven path) ----------------
#define KP2 20
__device__ __forceinline__ void mma_chunk(float acc[4][4],
                                          const uint32_t* __restrict__ A,
                                          const uint32_t* __restrict__ B,
                                          int wm, int wn, int lane) {
    const int g  = lane >> 2;
    const int tg = lane & 3;
#pragma unroll
    for (int s = 0; s < 2; s++) {
        const int kk = s * 8 + tg;
        const int ar = wm * 16 + g;
        uint32_t a0 = A[ar * KP2 + kk];
        uint32_t a1 = A[(ar + 8) * KP2 + kk];
        uint32_t a2 = A[ar * KP2 + kk + 4];
        uint32_t a3 = A[(ar + 8) * KP2 + kk + 4];
#pragma unroll
        for (int nn = 0; nn < 4; nn++) {
            const int br = wn * 32 + nn * 8 + g;
            mma_f16_frag(acc[nn], a0, a1, a2, a3, B[br * KP2 + kk], B[br * KP2 + kk + 4]);
        }
    }
}

__global__ void __launch_bounds__(256, 1) mlp1_kernel(const float* __restrict__ b1) {
    __shared__ uint32_t As[2][64][KP2];
    __shared__ uint32_t Bs[2][64][KP2];

    const int tid  = threadIdx.x;
    const int lane = tid & 31;
    const int warp = tid >> 5;
    const int wm   = warp >> 1;
    const int wn   = warp & 1;
    const int  n0   = blockIdx.x * 64;
    const long row0 = (long)blockIdx.y * 64;

    const int r0 = tid >> 2;
    const int sg = tid & 3;

    float acc[4][4];
#pragma unroll
    for (int i = 0; i < 4; i++)
#pragma unroll
        for (int j = 0; j < 4; j++) acc[i][j] = 0.0f;

    int4 aR = *reinterpret_cast<const int4*>(g_hs + (row0 + r0) * HID + sg * 8);
    int4 bR = *reinterpret_cast<const int4*>(g_w1_h + (long)(n0 + r0) * HID + sg * 8);
    *reinterpret_cast<int4*>(&As[0][r0][sg * 4]) = aR;
    *reinterpret_cast<int4*>(&Bs[0][r0][sg * 4]) = bR;
    __syncthreads();

    const int NK = HID / 32;
    for (int kc = 0; kc < NK; kc++) {
        if (kc + 1 < NK) {
            aR = *reinterpret_cast<const int4*>(
                     g_hs + (row0 + r0) * HID + (kc + 1) * 32 + sg * 8);
            bR = *reinterpret_cast<const int4*>(
                     g_w1_h + (long)(n0 + r0) * HID + (kc + 1) * 32 + sg * 8);
        }
        mma_chunk(acc, &As[kc & 1][0][0], &Bs[kc & 1][0][0], wm, wn, lane);
        if (kc + 1 < NK) {
            const int nb = (kc + 1) & 1;
            __syncthreads();
            *reinterpret_cast<int4*>(&As[nb][r0][sg * 4]) = aR;
            *reinterpret_cast<int4*>(&Bs[nb][r0][sg * 4]) = bR;
            __syncthreads();
        }
    }

    {
        const int cq = 2 * (lane & 3);
        const long rr = row0 + wm * 16 + (lane >> 2);
#pragma unroll
        for (int nn = 0; nn < 4; nn++) {
            const int col = n0 + wn * 32 + nn * 8 + cq;
            float bb0 = b1[col], bb1 = b1[col + 1];
            __half2 v0 = __floats2half2_rn(fmaxf(acc[nn][0] + bb0, 0.0f),
                                           fmaxf(acc[nn][1] + bb1, 0.0f));
            __half2 v1 = __floats2half2_rn(fmaxf(acc[nn][2] + bb0, 0.0f),
                                           fmaxf(acc[nn][3] + bb1, 0.0f));
            *reinterpret_cast<__half2*>(g_hid_h + rr * MLPH + col)       = v0;
            *reinterpret_cast<__half2*>(g_hid_h + (rr + 8) * MLPH + col) = v1;
        }
    }
}

// ---------------- MLP layer 2 + log_softmax (unpermutes t-major rows) ----------------
__global__ void __launch_bounds__(256, 2)
mlp2_kernel(const float* __restrict__ w2, const float* __restrict__ b2,
            float* __restrict__ out) {
    __shared__ float w2s[NCLS][MLPH + 1];
    __shared__ float hr[8][MLPH];

    const int tid  = threadIdx.x;
    const int lane = tid & 31;
    const int warp = tid >> 5;

    for (int e = tid; e < NCLS * MLPH; e += 256)
        w2s[e / MLPH][e % MLPH] = w2[e];

    const long row = (long)blockIdx.x * 8 + warp;   // = t*BATCH + b
    for (int k = lane; k < MLPH; k += 32)
        hr[warp][k] = __half2float(g_hid_h[row * MLPH + k]);
    __syncthreads();

    float logit = -1e30f;
    if (lane < NCLS) {
        float s = b2[lane];
#pragma unroll 8
        for (int k = 0; k < MLPH; k++)
            s += hr[warp][k] * w2s[lane][k];
        logit = s;
    }
    float m = logit;
#pragma unroll
    for (int o = 16; o; o >>= 1) m = fmaxf(m, __shfl_xor_sync(0xffffffffu, m, o));
    float e = (lane < NCLS) ? expf(logit - m) : 0.0f;
    float ssum = e;
#pragma unroll
    for (int o = 16; o; o >>= 1) ssum += __shfl_xor_sync(0xffffffffu, ssum, o);
    if (lane < NCLS) {
        const long b = row & (BATCH - 1);
        const long t = row >> 8;
        out[(b * SEQ + t) * NCLS + lane] = logit - m - logf(ssum);
    }
}

// ---------------- launch ----------------
extern "C" void kernel_launch(void* const* d_in, const int* in_sizes, int n_in,
                              void* d_out, int out_size) {
    const float* x    = (const float*)d_in[0];
    const float* w_ih = (const float*)d_in[1];
    const float* w_hh = (const float*)d_in[2];
    const float* b_ih = (const float*)d_in[3];
    const float* b_hh = (const float*)d_in[4];
    const float* w1   = (const float*)d_in[5];
    const float* b1   = (const float*)d_in[6];
    const float* w2   = (const float*)d_in[7];
    const float* b2   = (const float*)d_in[8];
    float* out = (float*)d_out;

    prep_kernel<<<(4 * HID * HID + 255) / 256, 256>>>(w_ih, w_hh, b_ih, b_hh, w1);
    prepx_kernel<<<((long)BATCH * SEQ * 64 + 255) / 256, 256>>>(x);

    cudaFuncSetAttribute(lstm_persist_kernel,
                         cudaFuncAttributeMaxDynamicSharedMemorySize, DSMEM);
    lstm_persist_kernel<<<NBLK, 256, DSMEM>>>();

    mlp1_kernel<<<dim3(MLPH / 64, (BATCH * SEQ) / 64), 256>>>(b1);
    mlp2_kernel<<<(BATCH * SEQ) / 8, 256>>>(w2, b2, out);
}